// round 1
// baseline (speedup 1.0000x reference)
#include <cuda_runtime.h>

#define DD 64          // feature dim
#define RPB 32         // rows per block
#define NTHREADS 256
#define RSLOTS 4       // NTHREADS / DD
#define RPT 8          // RPB / RSLOTS : rows per thread

__global__ __launch_bounds__(NTHREADS, 2)
void ragged_mm_kernel(const float* __restrict__ values,
                      const float* __restrict__ mats,
                      const int*   __restrict__ seg,
                      float*       __restrict__ out,
                      int T)
{
    __shared__ __align__(16) float v_sh[RPB * DD];

    const int base = blockIdx.x * RPB;
    if (base >= T) return;
    const int tid = threadIdx.x;
    const int j   = tid & (DD - 1);   // output column owned by this thread
    const int rs  = tid >> 6;         // row slot 0..3

    const int rows_here = min(RPB, T - base);

    // ---- stage values rows [base, base+rows_here) into shared (coalesced f4) ----
    {
        const float4* src = reinterpret_cast<const float4*>(values + (size_t)base * DD);
        float4* dst = reinterpret_cast<float4*>(v_sh);
        const int n4 = rows_here * (DD / 4);           // 512 when full
        for (int i = tid; i < n4; i += NTHREADS)
            dst[i] = src[i];
    }
    __syncthreads();

    const int s0 = seg[base];
    const int s1 = seg[base + rows_here - 1];

    float Mcol[DD];

    if (s0 == s1 && rows_here == RPB) {
        // ---------- fast path: whole block uses one matrix ----------
        const float* M = mats + (size_t)s0 * DD * DD + j;
        #pragma unroll
        for (int k = 0; k < DD; k++) Mcol[k] = M[k * DD];   // coalesced across lanes

        float acc[RPT];
        #pragma unroll
        for (int r = 0; r < RPT; r++) acc[r] = 0.0f;

        #pragma unroll
        for (int k4 = 0; k4 < DD / 4; k4++) {
            #pragma unroll
            for (int r = 0; r < RPT; r++) {
                const int row_l = rs + r * RSLOTS;
                float4 v = *reinterpret_cast<const float4*>(&v_sh[row_l * DD + k4 * 4]);
                acc[r] += v.x * Mcol[k4 * 4 + 0];
                acc[r] += v.y * Mcol[k4 * 4 + 1];
                acc[r] += v.z * Mcol[k4 * 4 + 2];
                acc[r] += v.w * Mcol[k4 * 4 + 3];
            }
        }

        #pragma unroll
        for (int r = 0; r < RPT; r++) {
            const int row = base + rs + r * RSLOTS;
            out[(size_t)row * DD + j] = acc[r];    // coalesced: consecutive j across lanes
        }
    } else {
        // ---------- rare path: block straddles a segment boundary (or tail) ----------
        int cur = -1;
        for (int r = 0; r < RPT; r++) {
            const int row_l = rs + r * RSLOTS;
            const int row   = base + row_l;
            if (row_l >= rows_here) break;
            const int s = seg[row];
            if (s != cur) {
                const float* M = mats + (size_t)s * DD * DD + j;
                #pragma unroll
                for (int k = 0; k < DD; k++) Mcol[k] = M[k * DD];
                cur = s;
            }
            float a0 = 0.f, a1 = 0.f, a2 = 0.f, a3 = 0.f;
            #pragma unroll
            for (int k4 = 0; k4 < DD / 4; k4++) {
                float4 v = *reinterpret_cast<const float4*>(&v_sh[row_l * DD + k4 * 4]);
                a0 += v.x * Mcol[k4 * 4 + 0];
                a1 += v.y * Mcol[k4 * 4 + 1];
                a2 += v.z * Mcol[k4 * 4 + 2];
                a3 += v.w * Mcol[k4 * 4 + 3];
            }
            out[(size_t)row * DD + j] = (a0 + a1) + (a2 + a3);
        }
    }
}

extern "C" void kernel_launch(void* const* d_in, const int* in_sizes, int n_in,
                              void* d_out, int out_size)
{
    const float* values = (const float*)d_in[0];   // [T, 64] f32
    const float* mats   = (const float*)d_in[1];   // [16, 64, 64] f32
    const int*   seg    = (const int*)d_in[2];     // [T] i32, sorted
    float*       out    = (float*)d_out;           // [T, 64] f32

    const int T = in_sizes[2];                     // seg length == T
    const int grid = (T + RPB - 1) / RPB;
    ragged_mm_kernel<<<grid, NTHREADS>>>(values, mats, seg, out, T);
}

// round 3
// speedup vs baseline: 1.3675x; 1.3675x over previous
#include <cuda_runtime.h>
#include <cstdint>

#define DD 64
#define RPB 64          // rows per block
#define NTHREADS 256

// Packed dual-FMA: d.lo = a.lo*b.lo + c.lo ; d.hi = a.hi*b.hi + c.hi
// NOTE: fma.rn.f32x2 takes .b64 operands -> must use "l" constraints, not "d".
__device__ __forceinline__ double ffma2(double a, double b, double c) {
    unsigned long long r;
    asm("fma.rn.f32x2 %0, %1, %2, %3;"
        : "=l"(r)
        : "l"(__double_as_longlong(a)),
          "l"(__double_as_longlong(b)),
          "l"(__double_as_longlong(c)));
    return __longlong_as_double(r);
}

__device__ __forceinline__ double pack2(float x) {
    float2 t = make_float2(x, x);
    long long ll;
    memcpy(&ll, &t, 8);
    return __longlong_as_double(ll);
}

__global__ __launch_bounds__(NTHREADS, 4)
void ragged_mm_f32x2(const float* __restrict__ values,
                     const float* __restrict__ mats,
                     const int*   __restrict__ seg,
                     float*       __restrict__ out,
                     int T)
{
    // v staged as duplicated (v,v) 8-byte pairs, row-major [r][k]  : 32 KB
    __shared__ __align__(16) double vdup[RPB * DD];
    // M staged in natural row-major [k][c]                          : 16 KB
    __shared__ __align__(16) float  Msh[DD * DD];

    const int base = blockIdx.x * RPB;
    if (base >= T) return;
    const int tid = threadIdx.x;
    const int c0  = (tid & 15) << 2;    // 4 output columns per thread
    const int r0  = (tid >> 4) << 2;    // 4 output rows per thread
    const int rows_here = min(RPB, T - base);

    // ---- stage values (coalesced float4) as duplicated pairs ----
    {
        const float4* src = reinterpret_cast<const float4*>(values + (size_t)base * DD);
        const int n4 = rows_here * (DD / 4);
        for (int i = tid; i < n4; i += NTHREADS) {
            float4 v = src[i];
            double2* dst = reinterpret_cast<double2*>(&vdup[i * 4]);
            dst[0] = make_double2(pack2(v.x), pack2(v.y));   // STS.128
            dst[1] = make_double2(pack2(v.z), pack2(v.w));   // STS.128
        }
    }

    const int s0 = seg[base];
    const int s1 = seg[base + rows_here - 1];

    // ---- stage matrix for s0 (fast path uses it; slow path ignores) ----
    {
        const float4* src = reinterpret_cast<const float4*>(mats + (size_t)s0 * DD * DD);
        float4* dst = reinterpret_cast<float4*>(Msh);
        for (int i = tid; i < DD * DD / 4; i += NTHREADS)
            dst[i] = src[i];
    }
    __syncthreads();

    if (s0 == s1 && rows_here == RPB) {
        // ---------------- fast path: single segment ----------------
        const double* Md = reinterpret_cast<const double*>(Msh);   // Md[k*32 + c/2] = (M[k][c], M[k][c+1])
        const int cpo = c0 >> 1;

        double acc00 = 0.0, acc01 = 0.0, acc10 = 0.0, acc11 = 0.0;
        double acc20 = 0.0, acc21 = 0.0, acc30 = 0.0, acc31 = 0.0;

        const double* v0 = &vdup[(r0 + 0) * DD];
        const double* v1 = &vdup[(r0 + 1) * DD];
        const double* v2 = &vdup[(r0 + 2) * DD];
        const double* v3 = &vdup[(r0 + 3) * DD];

        #pragma unroll 4
        for (int k = 0; k < DD; k += 2) {
            // M column-pairs for k and k+1 (LDS.128 each)
            double2 ma = *reinterpret_cast<const double2*>(Md + (k + 0) * 32 + cpo);
            double2 mb = *reinterpret_cast<const double2*>(Md + (k + 1) * 32 + cpo);
            // duplicated v pairs for 4 rows, 2 k's each (LDS.128 each)
            double2 b0 = *reinterpret_cast<const double2*>(v0 + k);
            double2 b1 = *reinterpret_cast<const double2*>(v1 + k);
            double2 b2 = *reinterpret_cast<const double2*>(v2 + k);
            double2 b3 = *reinterpret_cast<const double2*>(v3 + k);

            acc00 = ffma2(ma.x, b0.x, acc00);  acc01 = ffma2(ma.y, b0.x, acc01);
            acc10 = ffma2(ma.x, b1.x, acc10);  acc11 = ffma2(ma.y, b1.x, acc11);
            acc20 = ffma2(ma.x, b2.x, acc20);  acc21 = ffma2(ma.y, b2.x, acc21);
            acc30 = ffma2(ma.x, b3.x, acc30);  acc31 = ffma2(ma.y, b3.x, acc31);

            acc00 = ffma2(mb.x, b0.y, acc00);  acc01 = ffma2(mb.y, b0.y, acc01);
            acc10 = ffma2(mb.x, b1.y, acc10);  acc11 = ffma2(mb.y, b1.y, acc11);
            acc20 = ffma2(mb.x, b2.y, acc20);  acc21 = ffma2(mb.y, b2.y, acc21);
            acc30 = ffma2(mb.x, b3.y, acc30);  acc31 = ffma2(mb.y, b3.y, acc31);
        }

        // coalesced 16-byte stores: (c0..c0+3) for each of the 4 rows
        float* ob = out + (size_t)(base + r0) * DD + c0;
        *reinterpret_cast<double2*>(ob + 0 * DD) = make_double2(acc00, acc01);
        *reinterpret_cast<double2*>(ob + 1 * DD) = make_double2(acc10, acc11);
        *reinterpret_cast<double2*>(ob + 2 * DD) = make_double2(acc20, acc21);
        *reinterpret_cast<double2*>(ob + 3 * DD) = make_double2(acc30, acc31);
    } else {
        // -------- rare path: segment boundary / tail (≤15 blocks) --------
        const float* vf = reinterpret_cast<const float*>(vdup);  // vf[(r*64+k)*2] = v[r][k]
        for (int i = 0; i < 4; i++) {
            const int row_l = r0 + i;
            const int row   = base + row_l;
            if (row_l >= rows_here) break;
            const int s = seg[row];
            const float* M = mats + (size_t)s * DD * DD;
            float a0 = 0.f, a1 = 0.f, a2 = 0.f, a3 = 0.f;
            for (int k = 0; k < DD; k++) {
                float v = vf[(row_l * DD + k) * 2];
                const float* mrow = M + k * DD + c0;
                a0 += v * mrow[0];
                a1 += v * mrow[1];
                a2 += v * mrow[2];
                a3 += v * mrow[3];
            }
            float* o = out + (size_t)row * DD + c0;
            o[0] = a0; o[1] = a1; o[2] = a2; o[3] = a3;
        }
    }
}

extern "C" void kernel_launch(void* const* d_in, const int* in_sizes, int n_in,
                              void* d_out, int out_size)
{
    const float* values = (const float*)d_in[0];   // [T, 64] f32
    const float* mats   = (const float*)d_in[1];   // [16, 64, 64] f32
    const int*   seg    = (const int*)d_in[2];     // [T] i32 sorted
    float*       out    = (float*)d_out;           // [T, 64] f32

    const int T = in_sizes[2];
    const int grid = (T + RPB - 1) / RPB;
    ragged_mm_f32x2<<<grid, NTHREADS>>>(values, mats, seg, out, T);
}